// round 5
// baseline (speedup 1.0000x reference)
#include <cuda_runtime.h>
#include <cstdint>

// RoIPooling (TF2 crop_and_resize bilinear, POOL=7)
// feature_map: (1, 256, 256, 512) float32 NHWC
// proposals:   (512, 4) int32  [x, y, w, h]
// output:      (512, 7, 7, 512) float32
//
// R4: kernel is pinned at the LTS (L2 crossbar) byte cap (~6300 B/cyc):
// 257MB of L2 traffic / 11.3 TB/s = 22.8us, matching all prior variants.
// Only lever: fewer L2 bytes. Elide provably-redundant corner loads:
//   - fx==0 (w ≡ 7 mod 14, ~7% of boxes): x1 column has zero weight
//   - fy==0 (h ≡ 7 mod 14, ~7%): row1 has zero weight
//   - clamp collapse ix1==ix0 / iy1==iy0 (small boxes): duplicate pixel
// Substitutions (B:=A, G:=A, D:=B/G) feed bit-identical values into the
// same lerp chain -> numerics unchanged. All conditions are CTA-uniform.

#define POOL 7
#define FM_H 256
#define FM_W 256
#define FM_C 512
#define NPROP 512
#define C4 (FM_C / 4)

__global__ __launch_bounds__(128)
void roi_pool_kernel(const float* __restrict__ fm,
                     const int*   __restrict__ props,
                     float*       __restrict__ out)
{
    const int bid = blockIdx.x;           // 0 .. 3583
    const int n   = bid / POOL;
    const int py  = bid - n * POOL;

    const int4 box = reinterpret_cast<const int4*>(props)[n];
    const int bx = box.x, by = box.y, bw = box.z, bh = box.w;

    // --- y axis coords (match reference float32 math) ---
    const float hf = (float)bh;
    float sy = ((float)py + 0.5f) * (hf / (float)POOL) - 0.5f;
    sy = fminf(fmaxf(sy, 0.0f), hf - 1.0f);
    const int   iy0 = (int)floorf(sy);
    const int   iy1 = min(iy0 + 1, bh - 1);
    const float fy  = sy - (float)iy0;
    const float ofy = 1.0f - fy;

    // row1 contributes distinct bytes only if it is a different row AND has
    // nonzero weight. Otherwise reuse row0's registers (bit-identical math).
    const bool need_row1 = (iy1 != iy0) && (fy != 0.0f);

    const float4* __restrict__ row0 =
        reinterpret_cast<const float4*>(fm + ((size_t)(by + iy0) * FM_W + bx) * FM_C);
    const float4* __restrict__ row1 =
        reinterpret_cast<const float4*>(fm + ((size_t)(by + iy1) * FM_W + bx) * FM_C);

    const int c = threadIdx.x;            // float4 (channel-quad) index 0..127
    const float wf = (float)bw;
    const float xscale = wf / (float)POOL;

    float4* __restrict__ orow =
        reinterpret_cast<float4*>(out + ((size_t)n * (POOL * POOL) + (size_t)py * POOL) * FM_C);

    #pragma unroll
    for (int px = 0; px < POOL; ++px) {
        // --- x axis coords ---
        float sx = ((float)px + 0.5f) * xscale - 0.5f;
        sx = fminf(fmaxf(sx, 0.0f), wf - 1.0f);
        const int   ix0 = (int)floorf(sx);
        const int   ix1 = min(ix0 + 1, bw - 1);
        const float fx  = sx - (float)ix0;
        const float ofx = 1.0f - fx;

        // x1 column contributes distinct bytes only if different pixel AND
        // nonzero weight (fx==0 -> b*fx == +0 exactly; a*1 + 0 == a exactly).
        const bool need_x1 = (ix1 != ix0) && (fx != 0.0f);

        const float4 a = row0[ix0 * C4 + c];
        const float4 b = need_x1 ? row0[ix1 * C4 + c] : a;
        const float4 g = need_row1 ? row1[ix0 * C4 + c] : a;
        const float4 d = need_x1 ? (need_row1 ? row1[ix1 * C4 + c] : b) : g;

        float4 o;
        o.x = (a.x * ofx + b.x * fx) * ofy + (g.x * ofx + d.x * fx) * fy;
        o.y = (a.y * ofx + b.y * fx) * ofy + (g.y * ofx + d.y * fx) * fy;
        o.z = (a.z * ofx + b.z * fx) * ofy + (g.z * ofx + d.z * fx) * fy;
        o.w = (a.w * ofx + b.w * fx) * ofy + (g.w * ofx + d.w * fx) * fy;

        // streaming store: output is write-once, keep it out of L2's way
        __stcs(&orow[px * C4 + c], o);
    }
}

extern "C" void kernel_launch(void* const* d_in, const int* in_sizes, int n_in,
                              void* d_out, int out_size)
{
    const float* fm    = (const float*)d_in[0];
    const int*   props = (const int*)d_in[1];
    float*       out   = (float*)d_out;

    const int blocks = NPROP * POOL;      // 3584
    roi_pool_kernel<<<blocks, 128>>>(fm, props, out);
}

// round 7
// speedup vs baseline: 1.2074x; 1.2074x over previous
#include <cuda_runtime.h>
#include <cstdint>

// RoIPooling (TF2 crop_and_resize bilinear, POOL=7)
// feature_map: (1, 256, 256, 512) float32 NHWC
// proposals:   (512, 4) int32  [x, y, w, h]
// output:      (512, 7, 7, 512) float32
//
// R5: kernel sits on the chip LTS byte cap (~256MB L2 traffic / 11.2TB/s =
// 22.8us). R4 tried to elide redundant corner loads with per-px selects and
// regressed (load chain serialized). R5 does the same byte cut with
// CTA-UNIFORM branches into 4 specialized bodies, each containing only
// unconditional loads -> generic path is bit-for-bit the fast R2 body.
//   flag_y: fy==0 or iy1==iy0  -> row1 elided      (~7% of proposals)
//   flag_x: all px have fx==0 or ix1==ix0 -> x1 elided (~7%)
// Substituted values are bit-identical, numerics unchanged.

#define POOL 7
#define FM_H 256
#define FM_W 256
#define FM_C 512
#define NPROP 512
#define C4 (FM_C / 4)

template <bool NEED_X1, bool NEED_Y1>
__device__ __forceinline__
void roi_body(const float4* __restrict__ row0,
              const float4* __restrict__ row1,
              float4* __restrict__ orow,
              const int* __restrict__ ix0,
              const int* __restrict__ ix1,
              const float* __restrict__ fx,
              float fy, float ofy, int c)
{
    #pragma unroll
    for (int px = 0; px < POOL; ++px) {
        const float f  = fx[px];
        const float of = 1.0f - f;

        const float4 a = row0[ix0[px] * C4 + c];
        const float4 b = NEED_X1 ? row0[ix1[px] * C4 + c] : a;
        const float4 g = NEED_Y1 ? row1[ix0[px] * C4 + c] : a;
        const float4 d = NEED_Y1 ? (NEED_X1 ? row1[ix1[px] * C4 + c] : g) : b;

        float4 o;
        o.x = (a.x * of + b.x * f) * ofy + (g.x * of + d.x * f) * fy;
        o.y = (a.y * of + b.y * f) * ofy + (g.y * of + d.y * f) * fy;
        o.z = (a.z * of + b.z * f) * ofy + (g.z * of + d.z * f) * fy;
        o.w = (a.w * of + b.w * f) * ofy + (g.w * of + d.w * f) * fy;

        __stcs(&orow[px * C4 + c], o);
    }
}

__global__ __launch_bounds__(128)
void roi_pool_kernel(const float* __restrict__ fm,
                     const int*   __restrict__ props,
                     float*       __restrict__ out)
{
    const int bid = blockIdx.x;           // 0 .. 3583
    const int n   = bid / POOL;
    const int py  = bid - n * POOL;

    const int4 box = reinterpret_cast<const int4*>(props)[n];
    const int bx = box.x, by = box.y, bw = box.z, bh = box.w;

    // --- y axis coords (match reference float32 math) ---
    const float hf = (float)bh;
    float sy = ((float)py + 0.5f) * (hf / (float)POOL) - 0.5f;
    sy = fminf(fmaxf(sy, 0.0f), hf - 1.0f);
    const int   iy0 = (int)floorf(sy);
    const int   iy1 = min(iy0 + 1, bh - 1);
    const float fy  = sy - (float)iy0;
    const float ofy = 1.0f - fy;

    const bool need_y1 = (iy1 != iy0) && (fy != 0.0f);

    const float4* __restrict__ row0 =
        reinterpret_cast<const float4*>(fm + ((size_t)(by + iy0) * FM_W + bx) * FM_C);
    const float4* __restrict__ row1 =
        reinterpret_cast<const float4*>(fm + ((size_t)(by + iy1) * FM_W + bx) * FM_C);

    const int c = threadIdx.x;            // float4 (channel-quad) index 0..127
    const float wf = (float)bw;
    const float xscale = wf / (float)POOL;

    // --- x coords for all 7 cells + whole-CTA x1 flag ---
    int   ix0[POOL], ix1[POOL];
    float fx[POOL];
    bool  need_x1 = false;
    #pragma unroll
    for (int px = 0; px < POOL; ++px) {
        float sx = ((float)px + 0.5f) * xscale - 0.5f;
        sx = fminf(fmaxf(sx, 0.0f), wf - 1.0f);
        ix0[px] = (int)floorf(sx);
        ix1[px] = min(ix0[px] + 1, bw - 1);
        fx[px]  = sx - (float)ix0[px];
        // this px genuinely needs the x1 column?
        need_x1 |= ((ix1[px] != ix0[px]) && (fx[px] != 0.0f));
    }

    float4* __restrict__ orow =
        reinterpret_cast<float4*>(out + ((size_t)n * (POOL * POOL) + (size_t)py * POOL) * FM_C);

    // CTA-uniform dispatch (box-derived -> no divergence)
    if (need_x1) {
        if (need_y1) roi_body<true,  true >(row0, row1, orow, ix0, ix1, fx, fy, ofy, c);
        else         roi_body<true,  false>(row0, row1, orow, ix0, ix1, fx, fy, ofy, c);
    } else {
        if (need_y1) roi_body<false, true >(row0, row1, orow, ix0, ix1, fx, fy, ofy, c);
        else         roi_body<false, false>(row0, row1, orow, ix0, ix1, fx, fy, ofy, c);
    }
}

extern "C" void kernel_launch(void* const* d_in, const int* in_sizes, int n_in,
                              void* d_out, int out_size)
{
    const float* fm    = (const float*)d_in[0];
    const int*   props = (const int*)d_in[1];
    float*       out   = (float*)d_out;

    const int blocks = NPROP * POOL;      // 3584
    roi_pool_kernel<<<blocks, 128>>>(fm, props, out);
}

// round 8
// speedup vs baseline: 1.2450x; 1.0312x over previous
#include <cuda_runtime.h>
#include <cstdint>

// RoIPooling (TF2 crop_and_resize bilinear, POOL=7)
// feature_map: (1, 256, 256, 512) float32 NHWC
// proposals:   (512, 4) int32  [x, y, w, h]
// output:      (512, 7, 7, 512) float32
//
// R6: all register-scheduled variants pin at ~22.5-23us with no pipe >50%
// -> shared limiter is per-warp MLP (~4): ptxas reuses load dst registers
// across px cells, serializing loads behind blends. Fix: cp.async (LDGSTS)
// staging, register-free. Depth-4 pipeline over the 7 px cells; each thread
// stages its own 4x16B corner bytes into smem and reads them back itself
// (thread-private round trip -> NO barriers). 4 groups in flight = 32KB/CTA,
// ~7 CTAs/SM -> ~224KB in flight per SM vs ~84KB before.

#define POOL 7
#define FM_W 256
#define FM_C 512
#define NPROP 512
#define C4 (FM_C / 4)
#define DEPTH 4

__device__ __forceinline__ void cp16(uint32_t dst_smem, const void* src) {
    asm volatile("cp.async.cg.shared.global [%0], [%1], 16;\n"
                 :: "r"(dst_smem), "l"(src) : "memory");
}
__device__ __forceinline__ void cp_commit() {
    asm volatile("cp.async.commit_group;\n" ::: "memory");
}
template <int N>
__device__ __forceinline__ void cp_wait() {
    asm volatile("cp.async.wait_group %0;\n" :: "n"(N) : "memory");
}

struct Ctx {
    const float4* row0;
    const float4* row1;
    float4*       orow;
    float wf, xscale, fy, ofy;
    int   bw, c;
    uint32_t sbase;   // smem base address (bytes)
};

// x coords for cell px (bit-identical to reference float32 math)
__device__ __forceinline__ void xcoords(const Ctx& k, int px,
                                        int& ix0, int& ix1, float& fx) {
    float sx = ((float)px + 0.5f) * k.xscale - 0.5f;
    sx = fminf(fmaxf(sx, 0.0f), k.wf - 1.0f);
    ix0 = (int)floorf(sx);
    ix1 = min(ix0 + 1, k.bw - 1);
    fx  = sx - (float)ix0;
}

// stage slot layout: slot s, corner j, thread t at sbase + ((s*4+j)*128 + t)*16
__device__ __forceinline__ uint32_t slot_addr(const Ctx& k, int s, int j) {
    return k.sbase + (uint32_t)(((s * 4 + j) * 128 + k.c) * 16);
}

__device__ __forceinline__ void issue(const Ctx& k, int px) {
    int ix0, ix1; float fx;
    xcoords(k, px, ix0, ix1, fx);
    const int s = px & (DEPTH - 1);
    cp16(slot_addr(k, s, 0), &k.row0[ix0 * C4 + k.c]);
    cp16(slot_addr(k, s, 1), &k.row0[ix1 * C4 + k.c]);
    cp16(slot_addr(k, s, 2), &k.row1[ix0 * C4 + k.c]);
    cp16(slot_addr(k, s, 3), &k.row1[ix1 * C4 + k.c]);
    cp_commit();
}

template <int WC>
__device__ __forceinline__ void consume(const Ctx& k, const float4* buf, int px) {
    int ix0, ix1; float fx;
    xcoords(k, px, ix0, ix1, fx);          // recompute (cheap ALU, saves regs)
    const float of = 1.0f - fx;
    const int s = px & (DEPTH - 1);

    cp_wait<WC>();                          // stage px's group retired

    const float4 a = buf[(s * 4 + 0) * 128 + k.c];
    const float4 b = buf[(s * 4 + 1) * 128 + k.c];
    const float4 g = buf[(s * 4 + 2) * 128 + k.c];
    const float4 d = buf[(s * 4 + 3) * 128 + k.c];

    float4 o;
    o.x = (a.x * of + b.x * fx) * k.ofy + (g.x * of + d.x * fx) * k.fy;
    o.y = (a.y * of + b.y * fx) * k.ofy + (g.y * of + d.y * fx) * k.fy;
    o.z = (a.z * of + b.z * fx) * k.ofy + (g.z * of + d.z * fx) * k.fy;
    o.w = (a.w * of + b.w * fx) * k.ofy + (g.w * of + d.w * fx) * k.fy;

    __stcs(&k.orow[px * C4 + k.c], o);
}

__global__ __launch_bounds__(128)
void roi_pool_kernel(const float* __restrict__ fm,
                     const int*   __restrict__ props,
                     float*       __restrict__ out)
{
    __shared__ float4 buf[DEPTH * 4 * 128];    // 32 KB

    const int bid = blockIdx.x;                // 0 .. 3583
    const int n   = bid / POOL;
    const int py  = bid - n * POOL;

    const int4 box = reinterpret_cast<const int4*>(props)[n];
    const int bx = box.x, by = box.y, bw = box.z, bh = box.w;

    // --- y axis coords ---
    const float hf = (float)bh;
    float sy = ((float)py + 0.5f) * (hf / (float)POOL) - 0.5f;
    sy = fminf(fmaxf(sy, 0.0f), hf - 1.0f);
    const int   iy0 = (int)floorf(sy);
    const int   iy1 = min(iy0 + 1, bh - 1);

    Ctx k;
    k.fy  = sy - (float)iy0;
    k.ofy = 1.0f - k.fy;
    k.row0 = reinterpret_cast<const float4*>(fm + ((size_t)(by + iy0) * FM_W + bx) * FM_C);
    k.row1 = reinterpret_cast<const float4*>(fm + ((size_t)(by + iy1) * FM_W + bx) * FM_C);
    k.orow = reinterpret_cast<float4*>(out + ((size_t)n * (POOL * POOL) + (size_t)py * POOL) * FM_C);
    k.c   = threadIdx.x;
    k.bw  = bw;
    k.wf  = (float)bw;
    k.xscale = k.wf / (float)POOL;
    {
        uint32_t a;
        asm("{ .reg .u64 t; cvta.to.shared.u64 t, %1; cvt.u32.u64 %0, t; }"
            : "=r"(a) : "l"((const void*)buf));
        k.sbase = a;
    }

    // prologue: fill the pipe (4 stages in flight)
    issue(k, 0); issue(k, 1); issue(k, 2); issue(k, 3);

    // steady state + drain; wait counts keep exactly stage-px retired
    consume<3>(k, buf, 0); issue(k, 4);
    consume<3>(k, buf, 1); issue(k, 5);
    consume<3>(k, buf, 2); issue(k, 6);
    consume<3>(k, buf, 3);
    consume<2>(k, buf, 4);
    consume<1>(k, buf, 5);
    consume<0>(k, buf, 6);
}

extern "C" void kernel_launch(void* const* d_in, const int* in_sizes, int n_in,
                              void* d_out, int out_size)
{
    const float* fm    = (const float*)d_in[0];
    const int*   props = (const int*)d_in[1];
    float*       out   = (float*)d_out;

    const int blocks = NPROP * POOL;      // 3584
    roi_pool_kernel<<<blocks, 128>>>(fm, props, out);
}